// round 16
// baseline (speedup 1.0000x reference)
#include <cuda_runtime.h>
#include <cstdint>

// ---------------------------------------------------------------------------
// QLSTM fused persistent kernel, v12: table-lookup scan step.
//   * each gate uses only W[0,:]  -> theta is a scalar per batch element
//   * _expval(theta,U) = alpha + R*cos(theta - phi)
//   * f,i,g,o scalars per row -> c[b,:], h[b,:] uniform over hidden dim
// NEW: gate_g(theta) = sig/tanh(a_g + R_g cos(theta + tb_g)) is tabulated
// (2048 entries, value+slope, theta in [-8,8]) in shared memory. Workers
// pre-scale weights so the scan lookup is: u = fmaf(h, swS, zu); round via
// magic constant; LDS.64; lerp. 5 FMA ops per gate, zero MUFU.
// Roles (G = 2 x #SM, occ 2): block 0 = consts + tables + 128 scans
// (cp.async self-feed, 2-buffer ring); smid-sibling vacates; other blocks:
// chunk-major projection (credits) then gated broadcast.
// ---------------------------------------------------------------------------

#define T_STEPS 256
#define BATCH   128
#define ROWS    (T_STEPS * BATCH)     // 32768
#define DIMQ    256
#define NCH     8
#define CH_T    32                    // scan steps per credit/bcast chunk
#define CHROWS  (CH_T * BATCH)        // 4096 z-rows per chunk
#define REG4    (CHROWS * 128)        // float4 of output per chunk
#define SEQ_T   8                     // steps per smem buffer
#define NSEQ    (T_STEPS / SEQ_T)     // 32
#define NBUF    2                     // ring depth (2 x 8 x 128 x 16B = 32 KB)
#define TBLN    2048
#define TBL_BYTES (4 * TBLN * 8)      // 65536
#define RING_BYTES (NBUF * SEQ_T * BATCH * 16)  // 32768
#define TSCALE  127.9375f             // S = 2047/16
#define TOFF    1023.5f               // 8*S
#define MAGICF  12582912.0f           // 1.5 * 2^23
#define MAGICI  0x4B400000

__device__ float4   g_z[ROWS];        // per (t,b): pre-scaled table coords zu
__device__ float    g_h[ROWS];        // h, layout [b][t] (b*256 + t)
__device__ float    g_cfin[BATCH];    // final c per b
__device__ unsigned g_zcnt[NCH];      // z rows completed per chunk
__device__ unsigned g_dw[4];          // scan chunks completed per scan warp
__device__ unsigned g_b0smid;         // block 0's smid | 0x80000000
__device__ unsigned g_wrank;          // worker rank ticket

struct Args {
    const float* x;
    const float* W[4];
    const float* b[4];
    const float* P[4];
    float4* out;
    int G;
    int Wp;    // proj warps = (G-2)*8
    int n4;    // out_size / 4
};

// ---------------- sync primitives ----------------
__device__ __forceinline__ void red_release(unsigned* p, unsigned v) {
    asm volatile("red.release.gpu.add.u32 [%0], %1;" :: "l"(p), "r"(v) : "memory");
}
__device__ __forceinline__ unsigned ld_acq(const unsigned* p) {
    unsigned v;
    asm volatile("ld.acquire.gpu.u32 %0, [%1];" : "=r"(v) : "l"(p) : "memory");
    return v;
}
__device__ __forceinline__ void publish(unsigned* p, unsigned v) {
    asm volatile("fence.acq_rel.gpu;" ::: "memory");
    asm volatile("st.relaxed.gpu.u32 [%0], %1;" :: "l"(p), "r"(v) : "memory");
}
__device__ __forceinline__ void cp_async16(uint32_t dst_smem, const void* src) {
    asm volatile("cp.async.cg.shared.global [%0], [%1], 16;"
                 :: "r"(dst_smem), "l"(src) : "memory");
}
__device__ __forceinline__ void cp_commit() {
    asm volatile("cp.async.commit_group;" ::: "memory");
}
__device__ __forceinline__ void cp_wait1() {
    asm volatile("cp.async.wait_group 1;" ::: "memory");
}
__device__ __forceinline__ unsigned smid() {
    unsigned r;
    asm("mov.u32 %0, %%smid;" : "=r"(r));
    return r;
}

// ---------------- math helpers ----------------
__device__ __forceinline__ float2 cmul(float2 a, float2 b) {
    return make_float2(a.x * b.x - a.y * b.y, a.x * b.y + a.y * b.x);
}
__device__ __forceinline__ int chain_perm(int k) {   // CNOT chain = prefix-XOR
    k ^= k >> 1; k ^= k >> 2; k ^= k >> 4;
    return k & 0xFF;
}
__device__ __forceinline__ float rcpf(float x) {
    float r;
    asm("rcp.approx.f32 %0, %1;" : "=f"(r) : "f"(x));
    return r;
}
__device__ __forceinline__ float ex2f(float x) {
    float r;
    asm("ex2.approx.f32 %0, %1;" : "=f"(r) : "f"(x));
    return r;
}
__device__ __forceinline__ float tanh_hw(float x) {   // feedback only
    float r;
    asm("tanh.approx.f32 %0, %1;" : "=f"(r) : "f"(x));
    return r;
}

// ---------------- init (reset counters each replay) ----------------
__global__ void init_kernel() {
    int i = threadIdx.x;
    if (i < NCH) g_zcnt[i] = 0u;
    if (i < 4)  g_dw[i]   = 0u;
    if (i == 4) g_b0smid  = 0u;
    if (i == 5) g_wrank   = 0u;
}

// ---------------- fused kernel ----------------
__global__ void __launch_bounds__(256, 2) fused_kernel(Args a) {
    extern __shared__ unsigned char s_dyn[];   // [tables 64KB][ring 32KB]

    const int bid  = blockIdx.x;
    const int tid  = threadIdx.x;
    const int warp = tid >> 5, lane = tid & 31;

    // ============================ block 0 ============================
    if (bid == 0) {
        if (tid == 0) publish(&g_b0smid, smid() | 0x80000000u);

        float2* tbl  = reinterpret_cast<float2*>(s_dyn);
        float4* ring = reinterpret_cast<float4*>(s_dyn + TBL_BYTES);

        __shared__ float2 rot[2][8][2][2];
        __shared__ float2 u0[DIMQ];
        __shared__ float2 u1[DIMQ];
        __shared__ float  rbuf[4][8];
        __shared__ float  s_gate[4][5];        // alpha, R, phi, sW, b0

        const int k   = tid;
        const int pk0 = chain_perm(k);

        // -------- gate constants (all 256 threads, 4 gates) --------
        for (int g = 0; g < 4; ++g) {
            __syncthreads();
            const float* P = a.P[g];
            if (k < 16) {
                int l = k >> 3, w = k & 7;
                float phi = P[(l * 8 + w) * 3 + 0];
                float th  = P[(l * 8 + w) * 3 + 1];
                float om  = P[(l * 8 + w) * 3 + 2];
                float s, c;
                __sincosf(0.5f * th, &s, &c);
                float hp = 0.5f * (phi + om);
                float hm = 0.5f * (phi - om);
                float2 ep = make_float2(__cosf(hp), -__sinf(hp));
                float2 em = make_float2(__cosf(hm),  __sinf(hm));
                rot[l][w][0][0] = make_float2( ep.x * c,  ep.y * c);
                rot[l][w][0][1] = make_float2(-em.x * s, -em.y * s);
                rot[l][w][1][0] = make_float2( em.x * s, -em.y * s);
                rot[l][w][1][1] = make_float2( ep.x * c, -ep.y * c);
            }
            __syncthreads();

            float2 a0v = make_float2(1.f, 0.f);
            float2 a1v = make_float2(1.f, 0.f);
            #pragma unroll
            for (int w = 0; w < 8; ++w) {
                int kb = (k >> (7 - w)) & 1;
                a0v = cmul(a0v, rot[0][w][kb][0]);
                a1v = cmul(a1v, rot[0][w][kb][(w == 0) ? 1 : 0]);
            }
            u0[pk0] = a0v;
            u1[pk0] = a1v;
            __syncthreads();

            #pragma unroll
            for (int w = 0; w < 8; ++w) {
                int p = 7 - w, m = 1 << p, kb = (k >> p) & 1;
                float2 x0 = u0[k & ~m], x1 = u0[k | m];
                float2 y0 = u1[k & ~m], y1 = u1[k | m];
                __syncthreads();
                float2 r0 = rot[1][w][kb][0];
                float2 r1 = rot[1][w][kb][1];
                u0[k] = make_float2(r0.x * x0.x - r0.y * x0.y + r1.x * x1.x - r1.y * x1.y,
                                    r0.x * x0.y + r0.y * x0.x + r1.x * x1.y + r1.y * x1.x);
                u1[k] = make_float2(r0.x * y0.x - r0.y * y0.y + r1.x * y1.x - r1.y * y1.y,
                                    r0.x * y0.y + r0.y * y0.x + r1.x * y1.y + r1.y * y1.x);
                __syncthreads();
            }

            float2 c0 = u0[k], c1 = u1[k];
            __syncthreads();
            u0[pk0] = c0; u1[pk0] = c1;
            __syncthreads();
            c0 = u0[k]; c1 = u1[k];

            float z0 = (k < 128) ? 1.f : -1.f;
            float A  = z0 * (c0.x * c0.x + c0.y * c0.y);
            float Bv = z0 * (c1.x * c1.x + c1.y * c1.y);
            float Cv = -2.f * z0 * (c0.y * c1.x - c0.x * c1.y);
            const float* W = a.W[g];
            float sw = W[512 + k] + W[768 + k];

            float vals[4] = {A, Bv, Cv, sw};
            #pragma unroll
            for (int i = 0; i < 4; ++i) {
                float xv = vals[i];
                #pragma unroll
                for (int off = 16; off; off >>= 1)
                    xv += __shfl_xor_sync(0xffffffffu, xv, off);
                if (lane == 0) rbuf[i][warp] = xv;
            }
            __syncthreads();
            if (k == 0) {
                float t[4];
                #pragma unroll
                for (int i = 0; i < 4; ++i) {
                    float s = 0.f;
                    #pragma unroll
                    for (int wv = 0; wv < 8; ++wv) s += rbuf[i][wv];
                    t[i] = s;
                }
                float alpha = 0.5f * (t[0] + t[1]);
                float beta  = 0.5f * (t[0] - t[1]);
                float gamma = 0.5f * t[2];
                float R     = sqrtf(beta * beta + gamma * gamma);
                float phi   = (R > 0.f) ? atan2f(gamma, beta) : 0.f;
                s_gate[g][0] = alpha;
                s_gate[g][1] = R;
                s_gate[g][2] = phi;
                s_gate[g][3] = t[3];
                s_gate[g][4] = a.b[g][0];
            }
        }
        __syncthreads();

        // -------- build gate tables: value at k (accurate) --------
        {
            const float invS = 16.0f / 2047.0f;
            #pragma unroll
            for (int g = 0; g < 4; ++g) {
                const float ag = s_gate[g][0], Rg = s_gate[g][1];
                const float tb = s_gate[g][4] - s_gate[g][2];
                for (int kk = tid; kk < TBLN; kk += 256) {
                    float th = fmaf((float)kk, invS, -8.0f) + tb;
                    float E  = fmaf(Rg, cosf(th), ag);
                    float v;
                    if (g == 2) v = tanhf(E);
                    else        v = 1.0f / (1.0f + expf(-E));
                    tbl[g * TBLN + kk].x = v;
                }
            }
        }
        __syncthreads();
        // -------- slopes: central difference --------
        #pragma unroll
        for (int g = 0; g < 4; ++g) {
            for (int kk = tid; kk < TBLN; kk += 256) {
                int km = (kk > 0) ? kk - 1 : 0;
                int kp = (kk < TBLN - 1) ? kk + 1 : TBLN - 1;
                float scale = (kp - km == 2) ? 0.5f : 1.0f;
                tbl[g * TBLN + kk].y =
                    scale * (tbl[g * TBLN + kp].x - tbl[g * TBLN + km].x);
            }
        }
        __syncthreads();

        if (tid >= BATCH) return;   // warps 4-7 exit: scan SM stays quiet

        // ========== warps 0-3: table-driven self-feeding scan ==========
        const int b = tid;
        const float swSf = s_gate[0][3] * TSCALE;
        const float swSi = s_gate[1][3] * TSCALE;
        const float swSg = s_gate[2][3] * TSCALE;
        const float swSo = s_gate[3][3] * TSCALE;
        const float2* tf = tbl;
        const float2* ti = tbl + TBLN;
        const float2* tg = tbl + 2 * TBLN;
        const float2* to = tbl + 3 * TBLN;

        const uint32_t smem_base =
            (uint32_t)__cvta_generic_to_shared(ring) + (uint32_t)b * 16u;
        #define SLOT_ADDR(slot, s) (smem_base + ((uint32_t)(slot) * SEQ_T + (uint32_t)(s)) * (BATCH * 16u))

        // prologue: wait chunk 0 credit, issue buffers 0..1
        if (lane == 0) { while (ld_acq(&g_zcnt[0]) < (unsigned)CHROWS) {} }
        __syncwarp();
        #pragma unroll
        for (int q = 0; q < NBUF; ++q) {
            #pragma unroll
            for (int s = 0; s < SEQ_T; ++s)
                cp_async16(SLOT_ADDR(q, s), &g_z[(q * SEQ_T + s) * BATCH + b]);
            cp_commit();
        }

        float h = 0.f, cc = 0.f;
        float hbuf[SEQ_T];

        #define LOOKUP(res, swS, zu, tb_) { \
            float u  = fmaf(h, swS, zu); \
            float um = u + MAGICF; \
            int  idx = __float_as_int(um) - MAGICI; \
            float fr = u - (um - MAGICF); \
            float2 vc = (tb_)[idx]; \
            res = fmaf(fr, vc.y, vc.x); }

        #define QSTEP(ZV, S) { \
            float ff, ii, gg, oo; \
            LOOKUP(ff, swSf, (ZV).x, tf); \
            LOOKUP(ii, swSi, (ZV).y, ti); \
            LOOKUP(gg, swSg, (ZV).z, tg); \
            LOOKUP(oo, swSo, (ZV).w, to); \
            cc = fmaf(ff, cc, ii * gg); \
            h  = oo * tanh_hw(cc); \
            float es = ex2f(cc * 2.8853900817779268f); \
            hbuf[S] = oo * fmaf(-2.f, rcpf(es + 1.f), 1.f); \
        }

        float4* ringf = ring;
        for (int seq = 0; seq < NSEQ; ++seq) {
            cp_wait1();   // buffer `seq` complete (<=1 group pending)

            const float4* src = &ringf[(size_t)(seq & (NBUF - 1)) * SEQ_T * BATCH + b];
            float4 zv[SEQ_T];
            #pragma unroll
            for (int s = 0; s < SEQ_T; ++s) zv[s] = src[s * BATCH];

            const int nx = seq + NBUF;
            if (nx < NSEQ) {
                if ((nx & 3) == 0) {
                    const int c = nx >> 2;
                    if (lane == 0) { while (ld_acq(&g_zcnt[c]) < (unsigned)CHROWS) {} }
                    __syncwarp();
                }
                #pragma unroll
                for (int s = 0; s < SEQ_T; ++s)
                    cp_async16(SLOT_ADDR(nx & (NBUF - 1), s), &g_z[(nx * SEQ_T + s) * BATCH + b]);
            }
            cp_commit();   // uniform group count

            #pragma unroll
            for (int s = 0; s < SEQ_T; ++s) QSTEP(zv[s], s);

            // flush 8 h values: two STG.128 (g_h layout [b][t])
            {
                float4* hdst = reinterpret_cast<float4*>(&g_h[b * T_STEPS + seq * SEQ_T]);
                hdst[0] = make_float4(hbuf[0], hbuf[1], hbuf[2], hbuf[3]);
                hdst[1] = make_float4(hbuf[4], hbuf[5], hbuf[6], hbuf[7]);
            }

            if ((seq & 3) == 3) {
                __syncwarp();
                if (lane == 0) publish(&g_dw[warp], (unsigned)((seq >> 2) + 1));
            }
        }
        #undef QSTEP
        #undef LOOKUP
        #undef SLOT_ADDR
        g_cfin[b] = cc;
        __syncwarp();
        if (lane == 0) publish(&g_dw[warp], 8u);
        return;
    }

    // ============================ workers ============================
    __shared__ int s_wr;
    {
        if (tid == 0) {
            unsigned b0;
            while (((b0 = ld_acq(&g_b0smid)) & 0x80000000u) == 0u) {}
            if ((b0 & 0x7FFFFFFFu) == smid()) s_wr = -1;           // vacate
            else s_wr = (int)atomicAdd(&g_wrank, 1u);              // dense rank
        }
        __syncthreads();
        if (s_wr < 0) return;
    }
    const int wr = s_wr;

    // -------- PHASE 1: projection, chunk-major, scaled weights --------
    {
        const int gw = wr * 8 + warp;
        const float4* x4 = reinterpret_cast<const float4*>(a.x);

        float4 wv0[4], wv1[4], wv2[4], wv3[4];
        {
            const float4* W0 = reinterpret_cast<const float4*>(a.W[0]);
            const float4* W1 = reinterpret_cast<const float4*>(a.W[1]);
            const float4* W2 = reinterpret_cast<const float4*>(a.W[2]);
            const float4* W3 = reinterpret_cast<const float4*>(a.W[3]);
            #pragma unroll
            for (int it = 0; it < 4; ++it) {
                int e4 = it * 32 + lane;
                wv0[it] = W0[e4]; wv1[it] = W1[e4];
                wv2[it] = W2[e4]; wv3[it] = W3[e4];
                wv0[it].x *= TSCALE; wv0[it].y *= TSCALE; wv0[it].z *= TSCALE; wv0[it].w *= TSCALE;
                wv1[it].x *= TSCALE; wv1[it].y *= TSCALE; wv1[it].z *= TSCALE; wv1[it].w *= TSCALE;
                wv2[it].x *= TSCALE; wv2[it].y *= TSCALE; wv2[it].z *= TSCALE; wv2[it].w *= TSCALE;
                wv3[it].x *= TSCALE; wv3[it].y *= TSCALE; wv3[it].z *= TSCALE; wv3[it].w *= TSCALE;
            }
        }

        for (int c = 0; c < NCH; ++c) {
            const int cbase = c * CHROWS;
            int done = 0;
            for (int r = cbase + gw; r < cbase + CHROWS; r += a.Wp) {
                const float4* xr = x4 + (size_t)r * 128;
                float s0 = 0.f, s1 = 0.f, s2 = 0.f, s3 = 0.f;
                #pragma unroll
                for (int it = 0; it < 4; ++it) {
                    float4 xv = xr[it * 32 + lane];
                    s0 = fmaf(xv.x, wv0[it].x, s0); s0 = fmaf(xv.y, wv0[it].y, s0);
                    s0 = fmaf(xv.z, wv0[it].z, s0); s0 = fmaf(xv.w, wv0[it].w, s0);
                    s1 = fmaf(xv.x, wv1[it].x, s1); s1 = fmaf(xv.y, wv1[it].y, s1);
                    s1 = fmaf(xv.z, wv1[it].z, s1); s1 = fmaf(xv.w, wv1[it].w, s1);
                    s2 = fmaf(xv.x, wv2[it].x, s2); s2 = fmaf(xv.y, wv2[it].y, s2);
                    s2 = fmaf(xv.z, wv2[it].z, s2); s2 = fmaf(xv.w, wv2[it].w, s2);
                    s3 = fmaf(xv.x, wv3[it].x, s3); s3 = fmaf(xv.y, wv3[it].y, s3);
                    s3 = fmaf(xv.z, wv3[it].z, s3); s3 = fmaf(xv.w, wv3[it].w, s3);
                }
                #pragma unroll
                for (int off = 16; off; off >>= 1) {
                    s0 += __shfl_xor_sync(0xffffffffu, s0, off);
                    s1 += __shfl_xor_sync(0xffffffffu, s1, off);
                    s2 += __shfl_xor_sync(0xffffffffu, s2, off);
                    s3 += __shfl_xor_sync(0xffffffffu, s3, off);
                }
                if (lane == 0) {
                    // zu = clamp(z*S + 8S) into safe table coords
                    float z0c = fminf(fmaxf(s0 + TOFF, 384.f), 1663.f);
                    float z1c = fminf(fmaxf(s1 + TOFF, 384.f), 1663.f);
                    float z2c = fminf(fmaxf(s2 + TOFF, 384.f), 1663.f);
                    float z3c = fminf(fmaxf(s3 + TOFF, 384.f), 1663.f);
                    g_z[r] = make_float4(z0c, z1c, z2c, z3c);
                }
                ++done;
            }
            if (lane == 0 && done) red_release(&g_zcnt[c], (unsigned)done);
        }
    }

    // -------- PHASE 2: broadcast, chunk-by-chunk gated on g_dw --------
    {
        float4* out = a.out;
        const int stride = (a.G - 2) * 256;
        const int self   = wr * 256 + tid;

        for (int c = 0; c < NCH; ++c) {
            if (tid == 0) {
                while (ld_acq(&g_dw[0]) < (unsigned)(c + 1) ||
                       ld_acq(&g_dw[1]) < (unsigned)(c + 1) ||
                       ld_acq(&g_dw[2]) < (unsigned)(c + 1) ||
                       ld_acq(&g_dw[3]) < (unsigned)(c + 1)) __nanosleep(128);
            }
            __syncthreads();
            const int base = c * REG4;
            const int end  = base + REG4;
            #pragma unroll 2
            for (int i = base + self; i < end; i += stride) {
                int row = i >> 7;                                 // row = t*128 + b
                float v = g_h[((row & 127) << 8) | (row >> 7)];   // [b][t]
                out[i] = make_float4(v, v, v, v);
            }
        }
        // hx + cx
        const int base = NCH * REG4;   // == ROWS*128
        for (int i = base + self; i < a.n4; i += stride) {
            int row = i >> 7;
            float v;
            if (row < ROWS + BATCH) v = g_h[((row - ROWS) << 8) | 255]; // hx
            else                    v = g_cfin[row - ROWS - BATCH];     // cx
            out[i] = make_float4(v, v, v, v);
        }
    }
}

// ---------------- launch ----------------
extern "C" void kernel_launch(void* const* d_in, const int* in_sizes, int n_in,
                              void* d_out, int out_size) {
    static int s_sm = -1;
    const int DYN = TBL_BYTES + RING_BYTES;   // 96 KB
    if (s_sm < 0) {
        int dev = 0;
        cudaGetDevice(&dev);
        cudaDeviceGetAttribute(&s_sm, cudaDevAttrMultiProcessorCount, dev);
        if (s_sm <= 0) s_sm = 148;
        cudaFuncSetAttribute(fused_kernel,
                             cudaFuncAttributeMaxDynamicSharedMemorySize, DYN);
    }
    const int G  = 2 * s_sm;
    const int Wp = (G - 2) * 8;

    Args a;
    a.x = (const float*)d_in[0];
    a.W[0] = (const float*)d_in[1];  a.b[0] = (const float*)d_in[2];  a.P[0] = (const float*)d_in[3];
    a.W[1] = (const float*)d_in[4];  a.b[1] = (const float*)d_in[5];  a.P[1] = (const float*)d_in[6];
    a.W[2] = (const float*)d_in[7];  a.b[2] = (const float*)d_in[8];  a.P[2] = (const float*)d_in[9];
    a.W[3] = (const float*)d_in[10]; a.b[3] = (const float*)d_in[11]; a.P[3] = (const float*)d_in[12];
    a.out = (float4*)d_out;
    a.G   = G;
    a.Wp  = Wp;
    a.n4  = out_size / 4;

    init_kernel<<<1, 32>>>();
    fused_kernel<<<G, 256, DYN>>>(a);
}